// round 13
// baseline (speedup 1.0000x reference)
#include <cuda_runtime.h>
#include <cuda_fp16.h>
#include <cstdint>

#define N_MAX 50000
#define E_MAX 800000
#define SCAN_B 512
typedef unsigned long long ull;

// Scratch (device globals; only referenced from device code)
__device__ int   g_deg[N_MAX];
__device__ int   g_incl[N_MAX];
__device__ int   g_bsum[(N_MAX + SCAN_B - 1) / SCAN_B];
__device__ int   g_boff[(N_MAX + SCAN_B - 1) / SCAN_B];
__device__ int   g_rowptr[N_MAX + 1];
__device__ int   g_cursor[N_MAX];
__device__ float g_dinv[N_MAX];
__device__ int2  g_edge[E_MAX];                        // (src, norm bits) grouped by dst
__device__ __align__(16) float g_A[N_MAX * 64];        // GEMM output h (fp32)
__device__ __align__(16) float g_C[N_MAX * 64];        // layer activation
__device__ __align__(16) float g_s[3][64];             // fused BN scale per layer
__device__ __align__(16) float g_t[3][64];             // fused BN shift per layer

// ---------------- f32x2 helpers ----------------
__device__ __forceinline__ ull dupf(float w) {
    ull r; asm("mov.b64 %0, {%1, %1};" : "=l"(r) : "f"(w)); return r;
}
__device__ __forceinline__ void fma2acc(float2& d, ull a, ull b) {
    ull dd = *reinterpret_cast<ull*>(&d);
    asm("fma.rn.f32x2 %0, %1, %2, %0;" : "+l"(dd) : "l"(a), "l"(b));
    *reinterpret_cast<ull*>(&d) = dd;
}

// ---------------- degree count ----------------
__global__ void zero_deg_kernel(int n) {
    int i = blockIdx.x * blockDim.x + threadIdx.x;
    if (i < n) g_deg[i] = 0;
}

__global__ void count_deg_kernel(const int* __restrict__ dst, int E) {
    int i = blockIdx.x * blockDim.x + threadIdx.x;
    if (i < E) atomicAdd(&g_deg[dst[i]], 1);
}

// ---------------- prefix scan (warp-shuffle, + fused dinv) ----------------
__global__ void scan1_kernel(int n) {
    __shared__ int wsum[SCAN_B / 32];
    int gid = blockIdx.x * SCAN_B + threadIdx.x;
    int lane = threadIdx.x & 31, wid = threadIdx.x >> 5;
    int v = (gid < n) ? g_deg[gid] : 0;
    if (gid < n) g_dinv[gid] = rsqrtf((float)v + 1.0f);   // +1 self loop
    int x = v;
#pragma unroll
    for (int off = 1; off < 32; off <<= 1) {
        int t = __shfl_up_sync(0xFFFFFFFFu, x, off);
        if (lane >= off) x += t;
    }
    if (lane == 31) wsum[wid] = x;
    __syncthreads();
    if (wid == 0) {
        // all 32 lanes execute the shuffles; only first SCAN_B/32 carry data
        int s = (lane < SCAN_B / 32) ? wsum[lane] : 0;
#pragma unroll
        for (int off = 1; off < SCAN_B / 32; off <<= 1) {
            int t = __shfl_up_sync(0xFFFFFFFFu, s, off);
            if (lane >= off) s += t;
        }
        if (lane < SCAN_B / 32) wsum[lane] = s;
    }
    __syncthreads();
    int incl = x + (wid > 0 ? wsum[wid - 1] : 0);
    if (gid < n) g_incl[gid] = incl;
    if (threadIdx.x == SCAN_B - 1) g_bsum[blockIdx.x] = incl;
}

// exclusive scan of block sums (nb <= 128), warp-shuffle
__global__ void scan2_kernel(int nb) {
    __shared__ int wsum[4];
    int i = threadIdx.x;
    int lane = i & 31, wid = i >> 5;
    int v = (i < nb) ? g_bsum[i] : 0;
    int x = v;
#pragma unroll
    for (int off = 1; off < 32; off <<= 1) {
        int t = __shfl_up_sync(0xFFFFFFFFu, x, off);
        if (lane >= off) x += t;
    }
    if (lane == 31) wsum[wid] = x;
    __syncthreads();
    if (wid == 0) {
        // ALL 32 lanes run the shuffle (full-mask requirement); data in lanes 0..3
        int s = (lane < 4) ? wsum[lane] : 0;
#pragma unroll
        for (int off = 1; off < 4; off <<= 1) {
            int t = __shfl_up_sync(0xFFFFFFFFu, s, off);
            if (lane >= off) s += t;
        }
        if (lane < 4) wsum[lane] = s;
    }
    __syncthreads();
    int incl = x + (wid > 0 ? wsum[wid - 1] : 0);
    if (i < nb) g_boff[i] = incl - v;   // exclusive
}

__global__ void scan3_kernel(int n, int E) {
    int gid = blockIdx.x * blockDim.x + threadIdx.x;
    if (gid < n) {
        int rp = g_incl[gid] - g_deg[gid] + g_boff[gid / SCAN_B];
        g_rowptr[gid] = rp;
        g_cursor[gid] = rp;
    }
    if (gid == 0) g_rowptr[n] = E;
}

// ---------------- edge scatter (CSR by dst, norm precomputed) ----------------
__global__ void scatter_kernel(const int* __restrict__ src, const int* __restrict__ dst, int E) {
    int e = blockIdx.x * blockDim.x + threadIdx.x;
    if (e >= E) return;
    int s = src[e], d = dst[e];
    int pos = atomicAdd(&g_cursor[d], 1);
    g_edge[pos] = make_int2(s, __float_as_int(g_dinv[s] * g_dinv[d]));
}

// ---------------- fused BN prep for all 3 layers ----------------
__global__ void bn_prep_kernel(const float* __restrict__ b0, const float* __restrict__ ga0,
                               const float* __restrict__ be0, const float* __restrict__ m0,
                               const float* __restrict__ v0,
                               const float* __restrict__ b1, const float* __restrict__ ga1,
                               const float* __restrict__ be1, const float* __restrict__ m1,
                               const float* __restrict__ v1,
                               const float* __restrict__ b2) {
    int c = threadIdx.x;
    if (c < 64) {
        float s0 = ga0[c] * rsqrtf(v0[c] + 1e-5f);
        g_s[0][c] = s0; g_t[0][c] = (b0[c] - m0[c]) * s0 + be0[c];
        float s1 = ga1[c] * rsqrtf(v1[c] + 1e-5f);
        g_s[1][c] = s1; g_t[1][c] = (b1[c] - m1[c]) * s1 + be1[c];
        if (c < 40) { g_s[2][c] = 1.0f; g_t[2][c] = b2[c]; }
    }
}

// ---------------- GEMM: g_A[n,C] = X[n,K] @ W[K,C], f32x2 core ----------------
template<int K, int C, int KP, int BR>
__global__ void gemm_kernel(const float* __restrict__ x_ext, const float* __restrict__ W, int n) {
    constexpr int TY = BR / 8;
    constexpr int NTH = (C / 4) * TY;
    __shared__ __align__(16) float Ws[KP][C];
    __shared__ __align__(16) float Xs[KP][BR + 2];
    const float* X = x_ext ? x_ext : g_C;
    const int tid = threadIdx.y * (C / 4) + threadIdx.x;
    const int rowBlock = blockIdx.x * BR;
    const int tx = threadIdx.x;
    const int r0 = threadIdx.y * 8;

    float2 acc[4][4];
#pragma unroll
    for (int p = 0; p < 4; p++)
#pragma unroll
        for (int c = 0; c < 4; c++) acc[p][c] = make_float2(0.f, 0.f);

    for (int kp = 0; kp < K; kp += KP) {
        __syncthreads();
        for (int i = tid; i < KP * C / 4; i += NTH)
            ((float4*)&Ws[0][0])[i] = ((const float4*)(W + kp * C))[i];
        for (int i = tid; i < KP * BR / 4; i += NTH) {
            int r = i / (KP / 4);
            int q = i % (KP / 4);
            int row = rowBlock + r;
            float4 v = (row < n) ? *(const float4*)&X[(size_t)row * K + kp + q * 4]
                                 : make_float4(0.f, 0.f, 0.f, 0.f);
            Xs[q * 4 + 0][r] = v.x;
            Xs[q * 4 + 1][r] = v.y;
            Xs[q * 4 + 2][r] = v.z;
            Xs[q * 4 + 3][r] = v.w;
        }
        __syncthreads();
#pragma unroll 4
        for (int k = 0; k < KP; k++) {
            float4 w = *(const float4*)&Ws[k][tx * 4];
            ull wd0 = dupf(w.x), wd1 = dupf(w.y), wd2 = dupf(w.z), wd3 = dupf(w.w);
            const ull* xp = (const ull*)&Xs[k][r0];
#pragma unroll
            for (int p = 0; p < 4; p++) {
                ull a = xp[p];
                fma2acc(acc[p][0], a, wd0);
                fma2acc(acc[p][1], a, wd1);
                fma2acc(acc[p][2], a, wd2);
                fma2acc(acc[p][3], a, wd3);
            }
        }
    }
#pragma unroll
    for (int p = 0; p < 4; p++) {
        int row0 = rowBlock + r0 + 2 * p;
        if (row0 < n) {
            float4 o = make_float4(acc[p][0].x, acc[p][1].x, acc[p][2].x, acc[p][3].x);
            *(float4*)&g_A[(size_t)row0 * C + tx * 4] = o;
        }
        int row1 = row0 + 1;
        if (row1 < n) {
            float4 o = make_float4(acc[p][0].y, acc[p][1].y, acc[p][2].y, acc[p][3].y);
            *(float4*)&g_A[(size_t)row1 * C + tx * 4] = o;
        }
    }
}

// ---------------- fused CSR aggregation, C=64: 8 channels/thread, f32x2 ----------------
template<bool RELU>
__global__ void agg64_kernel(int layer, int n) {
    int node = blockIdx.x * blockDim.y + threadIdx.y;
    if (node >= n) return;
    const int c0 = threadIdx.x * 8;     // 8 lanes x 8 channels

    float2 acc[4];
    {
        float dv = g_dinv[node];
        ull sn = dupf(dv * dv);
        ulonglong2 ha = *(const ulonglong2*)&g_A[(size_t)node * 64 + c0];
        ulonglong2 hb = *(const ulonglong2*)&g_A[(size_t)node * 64 + c0 + 4];
#pragma unroll
        for (int i = 0; i < 4; i++) acc[i] = make_float2(0.f, 0.f);
        fma2acc(acc[0], ha.x, sn); fma2acc(acc[1], ha.y, sn);
        fma2acc(acc[2], hb.x, sn); fma2acc(acc[3], hb.y, sn);
    }

    int jb = g_rowptr[node], je = g_rowptr[node + 1];
    for (int j = jb; j < je; j++) {
        int2 ed = g_edge[j];
        ull wd = dupf(__int_as_float(ed.y));
        ulonglong2 ha = *(const ulonglong2*)&g_A[(size_t)ed.x * 64 + c0];
        ulonglong2 hb = *(const ulonglong2*)&g_A[(size_t)ed.x * 64 + c0 + 4];
        fma2acc(acc[0], ha.x, wd); fma2acc(acc[1], ha.y, wd);
        fma2acc(acc[2], hb.x, wd); fma2acc(acc[3], hb.y, wd);
    }

    const float2* s2 = (const float2*)&g_s[layer][c0];
    const float2* t2 = (const float2*)&g_t[layer][c0];
    float res[8];
#pragma unroll
    for (int i = 0; i < 4; i++) {
        float2 o;
        o.x = fmaf(acc[i].x, s2[i].x, t2[i].x);
        o.y = fmaf(acc[i].y, s2[i].y, t2[i].y);
        if (RELU) { o.x = fmaxf(o.x, 0.f); o.y = fmaxf(o.y, 0.f); }
        res[2 * i] = o.x; res[2 * i + 1] = o.y;
    }
    *(float4*)&g_C[(size_t)node * 64 + c0]     = *(float4*)&res[0];
    *(float4*)&g_C[(size_t)node * 64 + c0 + 4] = *(float4*)&res[4];
}

// ---------------- fused CSR aggregation, C=40 (final layer, bias only) ----------------
__global__ void agg40_kernel(float* __restrict__ out, int n) {
    constexpr int C = 40;
    int node = blockIdx.x * blockDim.y + threadIdx.y;
    if (node >= n) return;
    int lane = threadIdx.x;

    float dv = g_dinv[node];
    float sn = dv * dv;
    float4 acc = *(const float4*)&g_A[(size_t)node * C + lane * 4];
    acc.x *= sn; acc.y *= sn; acc.z *= sn; acc.w *= sn;

    int jb = g_rowptr[node], je = g_rowptr[node + 1];
    for (int j = jb; j < je; j++) {
        int2 ed = g_edge[j];
        float w = __int_as_float(ed.y);
        float4 hv = *(const float4*)&g_A[(size_t)ed.x * C + lane * 4];
        acc.x = fmaf(hv.x, w, acc.x);
        acc.y = fmaf(hv.y, w, acc.y);
        acc.z = fmaf(hv.z, w, acc.z);
        acc.w = fmaf(hv.w, w, acc.w);
    }

    float4 t = *(const float4*)&g_t[2][lane * 4];
    acc.x += t.x; acc.y += t.y; acc.z += t.z; acc.w += t.w;
    *(float4*)&out[(size_t)node * C + lane * 4] = acc;
}

static inline int cdiv(long long a, long long b) { return (int)((a + b - 1) / b); }

extern "C" void kernel_launch(void* const* d_in, const int* in_sizes, int n_in,
                              void* d_out, int out_size) {
    const float* x      = (const float*)d_in[0];
    const int*   ei     = (const int*)d_in[1];      // int32 [2, E]
    const float* W0     = (const float*)d_in[2];
    const float* b0     = (const float*)d_in[3];
    const float* gamma0 = (const float*)d_in[4];
    const float* beta0  = (const float*)d_in[5];
    const float* mean0  = (const float*)d_in[6];
    const float* var0   = (const float*)d_in[7];
    const float* W1     = (const float*)d_in[8];
    const float* b1     = (const float*)d_in[9];
    const float* gamma1 = (const float*)d_in[10];
    const float* beta1  = (const float*)d_in[11];
    const float* mean1  = (const float*)d_in[12];
    const float* var1   = (const float*)d_in[13];
    const float* W2     = (const float*)d_in[14];
    const float* b2     = (const float*)d_in[15];
    float* out = (float*)d_out;

    const int n = in_sizes[0] / 128;   // 50000
    const int E = in_sizes[1] / 2;     // 800000
    const int* src = ei;
    const int* dst = ei + E;

    const int T = 256;
    const int nb = cdiv(n, SCAN_B);

    // ---- GEMM0 first (independent of CSR build; same stream) ----
    {
        constexpr int K = 128, C = 64, KP = 64, BR = 64;
        gemm_kernel<K, C, KP, BR><<<cdiv(n, BR), dim3(C / 4, BR / 8)>>>(x, W0, n);
    }

    // ---- CSR build ----
    zero_deg_kernel<<<cdiv(n, T), T>>>(n);
    count_deg_kernel<<<cdiv(E, T), T>>>(dst, E);
    scan1_kernel<<<nb, SCAN_B>>>(n);
    scan2_kernel<<<1, 128>>>(nb);
    scan3_kernel<<<cdiv(n, T), T>>>(n, E);
    scatter_kernel<<<cdiv(E, T), T>>>(src, dst, E);
    bn_prep_kernel<<<1, 64>>>(b0, gamma0, beta0, mean0, var0,
                              b1, gamma1, beta1, mean1, var1, b2);

    // ---- layer pipeline ----
    agg64_kernel<true><<<cdiv(n, 32), dim3(8, 32)>>>(0, n);
    {
        constexpr int K = 64, C = 64, KP = 64, BR = 64;
        gemm_kernel<K, C, KP, BR><<<cdiv(n, BR), dim3(C / 4, BR / 8)>>>(nullptr, W1, n);
    }
    agg64_kernel<true><<<cdiv(n, 32), dim3(8, 32)>>>(1, n);
    {
        constexpr int K = 64, C = 40, KP = 64, BR = 64;
        gemm_kernel<K, C, KP, BR><<<cdiv(n, BR), dim3(C / 4, BR / 8)>>>(nullptr, W2, n);
    }
    agg40_kernel<<<cdiv(n, 25), dim3(10, 25)>>>(out, n);
}

// round 14
// speedup vs baseline: 1.1489x; 1.1489x over previous
#include <cuda_runtime.h>
#include <cuda_fp16.h>
#include <cstdint>

#define N_MAX 50000
#define E_MAX 800000
#define SCAN_B 512
typedef unsigned long long ull;

// Scratch (device globals; only referenced from device code)
__device__ int   g_deg[N_MAX];
__device__ int   g_incl[N_MAX];
__device__ int   g_bsum[(N_MAX + SCAN_B - 1) / SCAN_B];
__device__ int   g_boff[(N_MAX + SCAN_B - 1) / SCAN_B];
__device__ int   g_rowptr[N_MAX + 1];
__device__ int   g_cursor[N_MAX];
__device__ float g_dinv[N_MAX];
__device__ int2  g_edge[E_MAX];                        // (src, norm bits) grouped by dst
__device__ __align__(16) float g_A[N_MAX * 64];        // GEMM output h (fp32)
__device__ __align__(16) float g_C[N_MAX * 64];        // layer activation
__device__ __align__(16) float g_s[3][64];             // fused BN scale per layer
__device__ __align__(16) float g_t[3][64];             // fused BN shift per layer

// ---------------- f32x2 helpers ----------------
__device__ __forceinline__ ull dupf(float w) {
    ull r; asm("mov.b64 %0, {%1, %1};" : "=l"(r) : "f"(w)); return r;
}
__device__ __forceinline__ void fma2acc(float2& d, ull a, ull b) {
    ull dd = *reinterpret_cast<ull*>(&d);
    asm("fma.rn.f32x2 %0, %1, %2, %0;" : "+l"(dd) : "l"(a), "l"(b));
    *reinterpret_cast<ull*>(&d) = dd;
}

// ---------------- degree count ----------------
__global__ void zero_deg_kernel(int n) {
    int i = blockIdx.x * blockDim.x + threadIdx.x;
    if (i < n) g_deg[i] = 0;
}

__global__ void count_deg_kernel(const int* __restrict__ dst, int E) {
    int i = blockIdx.x * blockDim.x + threadIdx.x;
    if (i < E) atomicAdd(&g_deg[dst[i]], 1);
}

// ---------------- prefix scan (warp-shuffle, + fused dinv) ----------------
__global__ void scan1_kernel(int n) {
    __shared__ int wsum[SCAN_B / 32];
    int gid = blockIdx.x * SCAN_B + threadIdx.x;
    int lane = threadIdx.x & 31, wid = threadIdx.x >> 5;
    int v = (gid < n) ? g_deg[gid] : 0;
    if (gid < n) g_dinv[gid] = rsqrtf((float)v + 1.0f);   // +1 self loop
    int x = v;
#pragma unroll
    for (int off = 1; off < 32; off <<= 1) {
        int t = __shfl_up_sync(0xFFFFFFFFu, x, off);
        if (lane >= off) x += t;
    }
    if (lane == 31) wsum[wid] = x;
    __syncthreads();
    if (wid == 0) {
        // all 32 lanes execute the shuffles; only first SCAN_B/32 carry data
        int s = (lane < SCAN_B / 32) ? wsum[lane] : 0;
#pragma unroll
        for (int off = 1; off < SCAN_B / 32; off <<= 1) {
            int t = __shfl_up_sync(0xFFFFFFFFu, s, off);
            if (lane >= off) s += t;
        }
        if (lane < SCAN_B / 32) wsum[lane] = s;
    }
    __syncthreads();
    int incl = x + (wid > 0 ? wsum[wid - 1] : 0);
    if (gid < n) g_incl[gid] = incl;
    if (threadIdx.x == SCAN_B - 1) g_bsum[blockIdx.x] = incl;
}

// exclusive scan of block sums (nb <= 128), warp-shuffle (full-warp shuffles only)
__global__ void scan2_kernel(int nb) {
    __shared__ int wsum[4];
    int i = threadIdx.x;
    int lane = i & 31, wid = i >> 5;
    int v = (i < nb) ? g_bsum[i] : 0;
    int x = v;
#pragma unroll
    for (int off = 1; off < 32; off <<= 1) {
        int t = __shfl_up_sync(0xFFFFFFFFu, x, off);
        if (lane >= off) x += t;
    }
    if (lane == 31) wsum[wid] = x;
    __syncthreads();
    if (wid == 0) {
        int s = (lane < 4) ? wsum[lane] : 0;
#pragma unroll
        for (int off = 1; off < 4; off <<= 1) {
            int t = __shfl_up_sync(0xFFFFFFFFu, s, off);
            if (lane >= off) s += t;
        }
        if (lane < 4) wsum[lane] = s;
    }
    __syncthreads();
    int incl = x + (wid > 0 ? wsum[wid - 1] : 0);
    if (i < nb) g_boff[i] = incl - v;   // exclusive
}

__global__ void scan3_kernel(int n, int E) {
    int gid = blockIdx.x * blockDim.x + threadIdx.x;
    if (gid < n) {
        int rp = g_incl[gid] - g_deg[gid] + g_boff[gid / SCAN_B];
        g_rowptr[gid] = rp;
        g_cursor[gid] = rp;
    }
    if (gid == 0) g_rowptr[n] = E;
}

// ---------------- edge scatter (CSR by dst, norm precomputed) ----------------
__global__ void scatter_kernel(const int* __restrict__ src, const int* __restrict__ dst, int E) {
    int e = blockIdx.x * blockDim.x + threadIdx.x;
    if (e >= E) return;
    int s = src[e], d = dst[e];
    int pos = atomicAdd(&g_cursor[d], 1);
    g_edge[pos] = make_int2(s, __float_as_int(g_dinv[s] * g_dinv[d]));
}

// ---------------- fused BN prep for all 3 layers ----------------
__global__ void bn_prep_kernel(const float* __restrict__ b0, const float* __restrict__ ga0,
                               const float* __restrict__ be0, const float* __restrict__ m0,
                               const float* __restrict__ v0,
                               const float* __restrict__ b1, const float* __restrict__ ga1,
                               const float* __restrict__ be1, const float* __restrict__ m1,
                               const float* __restrict__ v1,
                               const float* __restrict__ b2) {
    int c = threadIdx.x;
    if (c < 64) {
        float s0 = ga0[c] * rsqrtf(v0[c] + 1e-5f);
        g_s[0][c] = s0; g_t[0][c] = (b0[c] - m0[c]) * s0 + be0[c];
        float s1 = ga1[c] * rsqrtf(v1[c] + 1e-5f);
        g_s[1][c] = s1; g_t[1][c] = (b1[c] - m1[c]) * s1 + be1[c];
        if (c < 40) { g_s[2][c] = 1.0f; g_t[2][c] = b2[c]; }
    }
}

// ---------------- GEMM: g_A[n,C] = X[n,K] @ W[K,C], f32x2 core ----------------
template<int K, int C, int KP, int BR>
__global__ void gemm_kernel(const float* __restrict__ x_ext, const float* __restrict__ W, int n) {
    constexpr int TY = BR / 8;
    constexpr int NTH = (C / 4) * TY;
    __shared__ __align__(16) float Ws[KP][C];
    __shared__ __align__(16) float Xs[KP][BR + 2];
    const float* X = x_ext ? x_ext : g_C;
    const int tid = threadIdx.y * (C / 4) + threadIdx.x;
    const int rowBlock = blockIdx.x * BR;
    const int tx = threadIdx.x;
    const int r0 = threadIdx.y * 8;

    float2 acc[4][4];
#pragma unroll
    for (int p = 0; p < 4; p++)
#pragma unroll
        for (int c = 0; c < 4; c++) acc[p][c] = make_float2(0.f, 0.f);

    for (int kp = 0; kp < K; kp += KP) {
        __syncthreads();
        for (int i = tid; i < KP * C / 4; i += NTH)
            ((float4*)&Ws[0][0])[i] = ((const float4*)(W + kp * C))[i];
        for (int i = tid; i < KP * BR / 4; i += NTH) {
            int r = i / (KP / 4);
            int q = i % (KP / 4);
            int row = rowBlock + r;
            float4 v = (row < n) ? *(const float4*)&X[(size_t)row * K + kp + q * 4]
                                 : make_float4(0.f, 0.f, 0.f, 0.f);
            Xs[q * 4 + 0][r] = v.x;
            Xs[q * 4 + 1][r] = v.y;
            Xs[q * 4 + 2][r] = v.z;
            Xs[q * 4 + 3][r] = v.w;
        }
        __syncthreads();
#pragma unroll 4
        for (int k = 0; k < KP; k++) {
            float4 w = *(const float4*)&Ws[k][tx * 4];
            ull wd0 = dupf(w.x), wd1 = dupf(w.y), wd2 = dupf(w.z), wd3 = dupf(w.w);
            const ull* xp = (const ull*)&Xs[k][r0];
#pragma unroll
            for (int p = 0; p < 4; p++) {
                ull a = xp[p];
                fma2acc(acc[p][0], a, wd0);
                fma2acc(acc[p][1], a, wd1);
                fma2acc(acc[p][2], a, wd2);
                fma2acc(acc[p][3], a, wd3);
            }
        }
    }
#pragma unroll
    for (int p = 0; p < 4; p++) {
        int row0 = rowBlock + r0 + 2 * p;
        if (row0 < n) {
            float4 o = make_float4(acc[p][0].x, acc[p][1].x, acc[p][2].x, acc[p][3].x);
            *(float4*)&g_A[(size_t)row0 * C + tx * 4] = o;
        }
        int row1 = row0 + 1;
        if (row1 < n) {
            float4 o = make_float4(acc[p][0].y, acc[p][1].y, acc[p][2].y, acc[p][3].y);
            *(float4*)&g_A[(size_t)row1 * C + tx * 4] = o;
        }
    }
}

// ---------------- fused CSR aggregation + self-loop + bias/BN/ReLU (R9 config) ----------------
template<int C, bool RELU>
__global__ void agg_kernel(int layer, float* __restrict__ out_ext, int n) {
    constexpr int Q = C / 4;
    int node = blockIdx.x * blockDim.y + threadIdx.y;
    if (node >= n) return;
    int lane = threadIdx.x;

    const float4* h4 = (const float4*)g_A;
    float dv = g_dinv[node];
    float sn = dv * dv;
    float4 acc = h4[(size_t)node * Q + lane];
    acc.x *= sn; acc.y *= sn; acc.z *= sn; acc.w *= sn;

    int jb = g_rowptr[node], je = g_rowptr[node + 1];
    for (int j = jb; j < je; j++) {
        int2 ed = g_edge[j];
        float w = __int_as_float(ed.y);
        float4 hv = h4[(size_t)ed.x * Q + lane];
        acc.x = fmaf(hv.x, w, acc.x);
        acc.y = fmaf(hv.y, w, acc.y);
        acc.z = fmaf(hv.z, w, acc.z);
        acc.w = fmaf(hv.w, w, acc.w);
    }

    float4 s = ((const float4*)&g_s[layer][0])[lane];
    float4 t = ((const float4*)&g_t[layer][0])[lane];
    float4 o;
    o.x = fmaf(acc.x, s.x, t.x);
    o.y = fmaf(acc.y, s.y, t.y);
    o.z = fmaf(acc.z, s.z, t.z);
    o.w = fmaf(acc.w, s.w, t.w);
    if (RELU) {
        o.x = fmaxf(o.x, 0.f); o.y = fmaxf(o.y, 0.f);
        o.z = fmaxf(o.z, 0.f); o.w = fmaxf(o.w, 0.f);
    }
    float* out = out_ext ? out_ext : g_C;
    *(float4*)&out[(size_t)node * C + lane * 4] = o;
}

static inline int cdiv(long long a, long long b) { return (int)((a + b - 1) / b); }

// Streams/events created once at static-init time (host objects only; no device memory).
struct HxStreams {
    cudaStream_t s1 = nullptr;
    cudaEvent_t  e0 = nullptr, e1 = nullptr;
    bool ok = false;
    HxStreams() {
        ok = (cudaStreamCreateWithFlags(&s1, cudaStreamNonBlocking) == cudaSuccess) &&
             (cudaEventCreateWithFlags(&e0, cudaEventDisableTiming) == cudaSuccess) &&
             (cudaEventCreateWithFlags(&e1, cudaEventDisableTiming) == cudaSuccess);
    }
};
static HxStreams hx;

extern "C" void kernel_launch(void* const* d_in, const int* in_sizes, int n_in,
                              void* d_out, int out_size) {
    const float* x      = (const float*)d_in[0];
    const int*   ei     = (const int*)d_in[1];      // int32 [2, E]
    const float* W0     = (const float*)d_in[2];
    const float* b0     = (const float*)d_in[3];
    const float* gamma0 = (const float*)d_in[4];
    const float* beta0  = (const float*)d_in[5];
    const float* mean0  = (const float*)d_in[6];
    const float* var0   = (const float*)d_in[7];
    const float* W1     = (const float*)d_in[8];
    const float* b1     = (const float*)d_in[9];
    const float* gamma1 = (const float*)d_in[10];
    const float* beta1  = (const float*)d_in[11];
    const float* mean1  = (const float*)d_in[12];
    const float* var1   = (const float*)d_in[13];
    const float* W2     = (const float*)d_in[14];
    const float* b2     = (const float*)d_in[15];
    float* out = (float*)d_out;

    const int n = in_sizes[0] / 128;   // 50000
    const int E = in_sizes[1] / 2;     // 800000
    const int* src = ei;
    const int* dst = ei + E;

    const int T = 256;
    const int nb = cdiv(n, SCAN_B);

    // ---- fork: GEMM0 (depends only on x, W0) on side stream, overlapping CSR build ----
    {
        constexpr int K = 128, C = 64, KP = 64, BR = 64;
        if (hx.ok) {
            cudaEventRecord(hx.e0, 0);
            cudaStreamWaitEvent(hx.s1, hx.e0, 0);
            gemm_kernel<K, C, KP, BR><<<cdiv(n, BR), dim3(C / 4, BR / 8), 0, hx.s1>>>(x, W0, n);
            cudaEventRecord(hx.e1, hx.s1);
        } else {
            gemm_kernel<K, C, KP, BR><<<cdiv(n, BR), dim3(C / 4, BR / 8)>>>(x, W0, n);
        }
    }

    // ---- CSR build on main stream ----
    zero_deg_kernel<<<cdiv(n, T), T>>>(n);
    count_deg_kernel<<<cdiv(E, T), T>>>(dst, E);
    scan1_kernel<<<nb, SCAN_B>>>(n);
    scan2_kernel<<<1, 128>>>(nb);
    scan3_kernel<<<cdiv(n, T), T>>>(n, E);
    scatter_kernel<<<cdiv(E, T), T>>>(src, dst, E);
    bn_prep_kernel<<<1, 64>>>(b0, gamma0, beta0, mean0, var0,
                              b1, gamma1, beta1, mean1, var1, b2);

    // ---- join ----
    if (hx.ok) cudaStreamWaitEvent(0, hx.e1, 0);

    // ---- layer pipeline (R9 agg config) ----
    agg_kernel<64, true><<<cdiv(n, 16), dim3(16, 16)>>>(0, nullptr, n);
    {
        constexpr int K = 64, C = 64, KP = 64, BR = 64;
        gemm_kernel<K, C, KP, BR><<<cdiv(n, BR), dim3(C / 4, BR / 8)>>>(nullptr, W1, n);
    }
    agg_kernel<64, true><<<cdiv(n, 16), dim3(16, 16)>>>(1, nullptr, n);
    {
        constexpr int K = 64, C = 40, KP = 64, BR = 64;
        gemm_kernel<K, C, KP, BR><<<cdiv(n, BR), dim3(C / 4, BR / 8)>>>(nullptr, W2, n);
    }
    agg_kernel<40, false><<<cdiv(n, 25), dim3(10, 25)>>>(2, out, n);
}